// round 17
// baseline (speedup 1.0000x reference)
#include <cuda_runtime.h>
#include <cuda_fp16.h>
#include <cstdint>

#define BB 4096
#define TT 512
#define IND 64
#define HH 10

#define NBAT 30              // batches per block
#define NCW  10              // consumer warps (3 batches each)
#define NPW  4               // producer warps
#define NTH  448             // 14 warps
#define NBLK 137             // ceil(4096/30)
#define NITER 66             // TT/8 + 2 pipeline stages

// smem layout (bytes): A double buffer (fp16 swizzled x), xg ring (fp16 gates)
#define A_BYTES  30720       // 240 rows x 64 halves x 2B
#define XG_BYTES 19200       // 240 rows x 40 halves x 2B
#define OFF_A0   0
#define OFF_A1   30720
#define OFF_XG0  61440
#define OFF_XG1  80640
#define SMEM_SZ  99840

// Pre-converted, pre-permuted fp16 W_ih (row g' = j*4+gate, UNswizzled) + bias
__device__ __align__(16) half whg[40 * 64];
__device__ float bsumg[40];

__device__ __forceinline__ void fma2(unsigned long long& d,
                                     unsigned long long a,
                                     unsigned long long b) {
    asm("fma.rn.f32x2 %0, %1, %2, %0;" : "+l"(d) : "l"(a), "l"(b));
}
#define PACK2(d, lo, hi) \
    asm("mov.b64 %0, {%1, %2};" : "=l"(d) : "f"(lo), "f"(hi))
#define UNPACK2(lo, hi, s) \
    asm("mov.b64 {%0, %1}, %2;" : "=f"(lo), "=f"(hi) : "l"(s))

__device__ __forceinline__ void mma16816(float* c, uint32_t a0, uint32_t a1,
                                         uint32_t a2, uint32_t a3,
                                         uint32_t b0, uint32_t b1)
{
    asm volatile(
        "mma.sync.aligned.m16n8k16.row.col.f32.f16.f16.f32 "
        "{%0,%1,%2,%3}, {%4,%5,%6,%7}, {%8,%9}, {%0,%1,%2,%3};"
        : "+f"(c[0]), "+f"(c[1]), "+f"(c[2]), "+f"(c[3])
        : "r"(a0), "r"(a1), "r"(a2), "r"(a3), "r"(b0), "r"(b1));
}

__device__ __forceinline__ float sigm_mufu(float x) {
    float t;
    asm("tanh.approx.f32 %0, %1;" : "=f"(t) : "f"(x * 0.5f));
    return fmaf(t, 0.5f, 0.5f);
}
__device__ __forceinline__ float tanh_mufu(float x) {
    float t;
    asm("tanh.approx.f32 %0, %1;" : "=f"(t) : "f"(x));
    return t;
}
__device__ __forceinline__ float tanh_fast(float x) {
    return 1.0f - 2.0f * __fdividef(1.0f, 1.0f + __expf(2.0f * x));
}

// ---------------------------------------------------------------------------
// K0: prep — W_ih to fp16, permute gate order (g' = j*4+gate), fold biases.
// ---------------------------------------------------------------------------
__global__ void prep_kernel(const float* __restrict__ W_ih,
                            const float* __restrict__ b_ih,
                            const float* __restrict__ b_hh)
{
    int e = blockIdx.x * 128 + threadIdx.x;
    if (e < 2560) {
        int g = e >> 6, k = e & 63;
        int gp = (g % 10) * 4 + g / 10;
        whg[gp * 64 + k] = __float2half_rn(W_ih[e]);
    }
    if (e < 40) {
        int gp = (e % 10) * 4 + e / 10;
        bsumg[gp] = b_ih[e] + b_hh[e];
    }
}

// ---------------------------------------------------------------------------
// Fused LSTM: producer warps (mma input projection) + consumer warps (scan)
// in one CTA, coupled by a double-buffered smem ring, one syncthreads/stage.
// ---------------------------------------------------------------------------
__global__ __launch_bounds__(NTH, 1)
void lstm_fused(const float* __restrict__ x,
                const float* __restrict__ W_hh,
                float* __restrict__ out)
{
    extern __shared__ char sm[];
    const int tid  = threadIdx.x;
    const int lane = tid & 31;
    const int wid  = tid >> 5;
    const int blk  = blockIdx.x;

    const int rgrp = lane >> 2;                    // mma row group / B row key
    const int kq   = lane & 3;

    // ---------------- consumer setup (wid < NCW) ----------------
    int group = lane / 10;
    const bool lactive = (lane < 30);
    if (!lactive) group = 2;
    const int j = lactive ? (lane - group * 10) : 0;
    const int b = blk * NBAT + wid * 3 + group;
    const bool valid = (wid < NCW) && lactive && (b < BB);
    const int b_eff = (b < BB) ? b : 0;
    const int srcbase = group * 10;
    const int xrow_base = (wid * 3 + group) * 8;   // ring row base for my batch

    unsigned long long wIF[10], wGO[10];
    if (wid < NCW) {
        #pragma unroll
        for (int k = 0; k < 10; ++k) {
            PACK2(wIF[k], W_hh[(j)      * HH + k], W_hh[(j + 10) * HH + k]);
            PACK2(wGO[k], W_hh[(j + 20) * HH + k], W_hh[(j + 30) * HH + k]);
        }
    }
    float h = 0.0f, c = 0.0f;
    float* outp = out + (size_t)b_eff * TT * HH + j;

    // ---------------- producer setup (wid >= NCW) ----------------
    uint32_t bf0[4][5], bf1[4][5];                 // B fragments, resident
    float2 bp[5];
    const int ptid = tid - NCW * 32;               // 0..127 producer thread id
    const int pw   = wid - NCW;                    // 0..3 producer warp id
    if (wid >= NCW) {
        const uint32_t* wg32 = (const uint32_t*)whg;
        #pragma unroll
        for (int ks = 0; ks < 4; ++ks)
            #pragma unroll
            for (int n = 0; n < 5; ++n) {
                int g = n * 8 + rgrp;
                bf0[ks][n] = wg32[g * 32 + 8 * ks + kq];       // k0+2kq
                bf1[ks][n] = wg32[g * 32 + 8 * ks + 4 + kq];   // k0+8+2kq
            }
        #pragma unroll
        for (int n = 0; n < 5; ++n)
            bp[n] = *(const float2*)&bsumg[n * 8 + 2 * kq];
    }

    // ---------------- pipelined main loop ----------------
    // iter i:  producers load x(stage i)->A[i&1];  MMA A[(i-1)&1]->xg[(i-1)&1];
    //          consumers eat xg[(i-2)&1] (stage i-2).  One sync per iter.
    for (int i = 0; i < NITER; ++i) {
        __syncthreads();

        if (wid >= NCW) {
            // ---- MMA phase: stage i-1 ----
            if (i >= 1 && i <= TT / 8) {
                const half* Ab = (const half*)(sm + (((i - 1) & 1) ? OFF_A1 : OFF_A0));
                __half2* xgb = (__half2*)(sm + (((i - 1) & 1) ? OFF_XG1 : OFF_XG0));
                #pragma unroll 4
                for (int m = pw; m < 15; m += NPW) {
                    float acc[5][4];
                    #pragma unroll
                    for (int n = 0; n < 5; ++n)
                        #pragma unroll
                        for (int q = 0; q < 4; ++q) acc[n][q] = 0.0f;
                    const int ra = 16 * m + rgrp;
                    #pragma unroll
                    for (int ks = 0; ks < 4; ++ks) {
                        const int ch0 = ((2 * ks)     ^ rgrp) * 8 + 2 * kq;
                        const int ch1 = ((2 * ks + 1) ^ rgrp) * 8 + 2 * kq;
                        uint32_t a0 = *(const uint32_t*)&Ab[ra * 64 + ch0];
                        uint32_t a1 = *(const uint32_t*)&Ab[(ra + 8) * 64 + ch0];
                        uint32_t a2 = *(const uint32_t*)&Ab[ra * 64 + ch1];
                        uint32_t a3 = *(const uint32_t*)&Ab[(ra + 8) * 64 + ch1];
                        #pragma unroll
                        for (int n = 0; n < 5; ++n)
                            mma16816(acc[n], a0, a1, a2, a3, bf0[ks][n], bf1[ks][n]);
                    }
                    #pragma unroll
                    for (int n = 0; n < 5; ++n) {
                        const int cn = n * 8 + 2 * kq;
                        __half2 o0 = __floats2half2_rn(acc[n][0] + bp[n].x,
                                                       acc[n][1] + bp[n].y);
                        __half2 o1 = __floats2half2_rn(acc[n][2] + bp[n].x,
                                                       acc[n][3] + bp[n].y);
                        xgb[ra * 20 + (cn >> 1)]       = o0;
                        xgb[(ra + 8) * 20 + (cn >> 1)] = o1;
                    }
                }
            }
            // ---- load phase: x(stage i) -> A[i&1], fp16 chunk-XOR swizzle ----
            if (i < TT / 8) {
                half* Aw = (half*)(sm + ((i & 1) ? OFF_A1 : OFF_A0));
                #pragma unroll
                for (int ii = 0; ii < 15; ++ii) {           // 1920 chunks / 128 thr
                    int idx = ptid + ii * 128;
                    int r = idx >> 3, cc = idx & 7;
                    int bl = r >> 3, u = r & 7;
                    int bb = blk * NBAT + bl; if (bb >= BB) bb = BB - 1;
                    const float4* xr =
                        (const float4*)(x + ((size_t)bb * TT + i * 8 + u) * IND);
                    float4 v0 = __ldcs(&xr[cc * 2]);
                    float4 v1 = __ldcs(&xr[cc * 2 + 1]);
                    __half2 p0 = __floats2half2_rn(v0.x, v0.y);
                    __half2 p1 = __floats2half2_rn(v0.z, v0.w);
                    __half2 p2 = __floats2half2_rn(v1.x, v1.y);
                    __half2 p3 = __floats2half2_rn(v1.z, v1.w);
                    uint4 pk;
                    pk.x = *(const uint32_t*)&p0;
                    pk.y = *(const uint32_t*)&p1;
                    pk.z = *(const uint32_t*)&p2;
                    pk.w = *(const uint32_t*)&p3;
                    *(uint4*)&Aw[r * 64 + ((cc ^ u) << 3)] = pk;
                }
            }
        } else if (i >= 2) {
            // ---- consumer: scan stage i-2 from the ring ----
            const uint2* xgu = (const uint2*)(sm + ((i & 1) ? OFF_XG1 : OFF_XG0));
            uint2 pf[8];
            #pragma unroll
            for (int u = 0; u < 8; ++u)
                pf[u] = xgu[(xrow_base + u) * 10 + j];

            const int t0 = (i - 2) * 8;
            #pragma unroll
            for (int u = 0; u < 8; ++u) {
                float2 fIF = __half22float2(*(const __half2*)&pf[u].x);  // (i,f)
                float2 fGO = __half22float2(*(const __half2*)&pf[u].y);  // (g,o)
                unsigned long long aIF, aGO;
                PACK2(aIF, fIF.x, fIF.y);
                PACK2(aGO, fGO.x, fGO.y);
                #pragma unroll
                for (int k = 0; k < 10; ++k) {
                    float hk = __shfl_sync(0xffffffffu, h, srcbase + k);
                    unsigned long long hd;
                    PACK2(hd, hk, hk);
                    fma2(aIF, hd, wIF[k]);
                    fma2(aGO, hd, wGO[k]);
                }
                float aI, aF, aG, aO;
                UNPACK2(aI, aF, aIF);
                UNPACK2(aG, aO, aGO);

                float ig = sigm_mufu(aI);
                float fg = sigm_mufu(aF);
                float gg = tanh_mufu(aG);
                float og = sigm_mufu(aO);
                c = fmaf(fg, c, ig * gg);
                h = og * tanh_fast(c);

                if (valid)
                    __stcs(&outp[(size_t)(t0 + u) * HH], h);
            }
        }
    }

    if (valid)
        out[(size_t)BB * TT * HH + (size_t)b * HH + j] = h;
}

// ---------------------------------------------------------------------------
extern "C" void kernel_launch(void* const* d_in, const int* in_sizes, int n_in,
                              void* d_out, int out_size)
{
    const float* x    = (const float*)d_in[0];
    const float* W_ih = (const float*)d_in[1];
    const float* W_hh = (const float*)d_in[2];
    const float* b_ih = (const float*)d_in[3];
    const float* b_hh = (const float*)d_in[4];
    float* out = (float*)d_out;

    static bool attr_done = false;
    if (!attr_done) {
        cudaFuncSetAttribute(lstm_fused,
                             cudaFuncAttributeMaxDynamicSharedMemorySize, SMEM_SZ);
        attr_done = true;
    }

    prep_kernel<<<20, 128>>>(W_ih, b_ih, b_hh);
    lstm_fused<<<NBLK, NTH, SMEM_SZ>>>(x, W_hh, out);
}